// round 2
// baseline (speedup 1.0000x reference)
#include <cuda_runtime.h>
#include <float.h>

#define BN 512
#define DN 256

// Scratch (no allocations allowed in kernel_launch)
__device__ float g_pd[BN * BN];
__device__ float g_sq[BN];
__device__ float g_ploss[BN];
__device__ int   g_pcnt[BN];

// ---------------------------------------------------------------------------
// Kernel 1: squared row norms. One block per row, 256 threads (one per dim).
// ---------------------------------------------------------------------------
__global__ void sq_kernel(const float* __restrict__ emb) {
    const int j = blockIdx.x;
    const int tid = threadIdx.x;
    float v = emb[j * DN + tid];
    float s = v * v;
    #pragma unroll
    for (int o = 16; o; o >>= 1) s += __shfl_xor_sync(0xffffffffu, s, o);
    __shared__ float ws[8];
    if ((tid & 31) == 0) ws[tid >> 5] = s;
    __syncthreads();
    if (tid == 0) {
        float t = 0.f;
        #pragma unroll
        for (int i = 0; i < 8; i++) t += ws[i];
        g_sq[j] = t;
    }
}

// ---------------------------------------------------------------------------
// Kernel 2: pairwise squared distances.
// pd[i][j] = max(sq[i] + sq[j] - 2 * dot(emb_i, emb_j), 0), diag = 0.
// 64x64 tile per block, 256 threads, 4x4 microtile per thread, K-chunk 16.
// ---------------------------------------------------------------------------
__global__ void pd_kernel(const float* __restrict__ emb) {
    __shared__ float As[16][64];
    __shared__ float Bs[16][64];
    const int tid = threadIdx.x;
    const int tx = tid & 15, ty = tid >> 4;
    const int i0 = blockIdx.y * 64, j0 = blockIdx.x * 64;
    const int lr = tid >> 2;          // row within tile 0..63
    const int lk = (tid & 3) << 2;    // k offset within chunk: 0,4,8,12

    float acc[4][4] = {};

    for (int k0 = 0; k0 < DN; k0 += 16) {
        float4 a = *(const float4*)(emb + (i0 + lr) * DN + k0 + lk);
        float4 b = *(const float4*)(emb + (j0 + lr) * DN + k0 + lk);
        __syncthreads();
        As[lk + 0][lr] = a.x; As[lk + 1][lr] = a.y;
        As[lk + 2][lr] = a.z; As[lk + 3][lr] = a.w;
        Bs[lk + 0][lr] = b.x; Bs[lk + 1][lr] = b.y;
        Bs[lk + 2][lr] = b.z; Bs[lk + 3][lr] = b.w;
        __syncthreads();
        #pragma unroll
        for (int kk = 0; kk < 16; kk++) {
            float4 av = *(const float4*)&As[kk][ty << 2];
            float4 bv = *(const float4*)&Bs[kk][tx << 2];
            float ar[4] = {av.x, av.y, av.z, av.w};
            float br[4] = {bv.x, bv.y, bv.z, bv.w};
            #pragma unroll
            for (int u = 0; u < 4; u++)
                #pragma unroll
                for (int v = 0; v < 4; v++)
                    acc[u][v] = fmaf(ar[u], br[v], acc[u][v]);
        }
    }

    float sqi[4], sqj[4];
    #pragma unroll
    for (int u = 0; u < 4; u++) sqi[u] = g_sq[i0 + (ty << 2) + u];
    #pragma unroll
    for (int v = 0; v < 4; v++) sqj[v] = g_sq[j0 + (tx << 2) + v];

    #pragma unroll
    for (int u = 0; u < 4; u++) {
        const int gi = i0 + (ty << 2) + u;
        float ov[4];
        #pragma unroll
        for (int v = 0; v < 4; v++) {
            const int gj = j0 + (tx << 2) + v;
            float d = fmaxf(sqi[u] + sqj[v] - 2.f * acc[u][v], 0.f);
            if (gi == gj) d = 0.f;
            ov[v] = d;
        }
        float4 o = make_float4(ov[0], ov[1], ov[2], ov[3]);
        *(float4*)(g_pd + gi * BN + j0 + (tx << 2)) = o;
    }
}

// ---------------------------------------------------------------------------
// Kernel 3: semi-hard mining per anchor. One CTA (256 thr) per anchor j.
// For each positive i (same label, i != j):
//   neg_outside = min_k { pd[j,k] : label[k] != label[j] && pd[j,k] > pd[j,i] }
//   semi = neg_outside if any valid k else neg_inside[j]
//   neg_inside[j] = max over negatives (fallback rowmin if no negatives)
//   partial_loss += relu(1 + pd[j,i] - semi)
// Labels are int32 (JAX x64 disabled -> int64 request silently becomes int32).
// ---------------------------------------------------------------------------
__global__ void mine_kernel(const int* __restrict__ labels) {
    const int j = blockIdx.x;
    const int tid = threadIdx.x;     // 256 threads
    const int lane = tid & 31, wid = tid >> 5;

    __shared__ float row[BN];
    __shared__ unsigned char issame[BN];
    __shared__ float s_mx[8], s_mn[8], s_wsum[8];
    __shared__ float s_neg_inside;

    const int lj = labels[j];
    float lmaxneg = -FLT_MAX;
    float lmin = FLT_MAX;
    #pragma unroll
    for (int k = tid; k < BN; k += 256) {
        float v = g_pd[j * BN + k];
        row[k] = v;
        const bool same = (labels[k] == lj);
        issame[k] = same ? 1 : 0;
        if (!same) lmaxneg = fmaxf(lmaxneg, v);
        lmin = fminf(lmin, v);
    }
    #pragma unroll
    for (int o = 16; o; o >>= 1) {
        lmaxneg = fmaxf(lmaxneg, __shfl_xor_sync(0xffffffffu, lmaxneg, o));
        lmin    = fminf(lmin,    __shfl_xor_sync(0xffffffffu, lmin,    o));
    }
    if (lane == 0) { s_mx[wid] = lmaxneg; s_mn[wid] = lmin; }
    __syncthreads();
    if (tid == 0) {
        float mx = -FLT_MAX, mn = FLT_MAX;
        #pragma unroll
        for (int w = 0; w < 8; w++) { mx = fmaxf(mx, s_mx[w]); mn = fminf(mn, s_mn[w]); }
        s_neg_inside = (mx > -FLT_MAX) ? mx : mn;  // fallback if no negatives
    }
    __syncthreads();

    const float ninside = s_neg_inside;
    float wsum = 0.f;
    int wcnt = 0;
    // Deterministic warp-per-positive: warp w handles candidate i = w, w+8, ...
    for (int i = wid; i < BN; i += 8) {
        if (!issame[i] || i == j) continue;
        wcnt++;
        const float t = row[i];
        float m = FLT_MAX;
        #pragma unroll
        for (int k = lane; k < BN; k += 32) {
            const float v = row[k];
            if (!issame[k] && v > t) m = fminf(m, v);
        }
        #pragma unroll
        for (int o = 16; o; o >>= 1) m = fminf(m, __shfl_xor_sync(0xffffffffu, m, o));
        const float semi = (m < FLT_MAX) ? m : ninside;
        if (lane == 0) wsum += fmaxf(1.0f + t - semi, 0.f);
    }
    if (lane == 0) { s_wsum[wid] = wsum; }
    __shared__ int s_wcnt[8];
    if (lane == 0) { s_wcnt[wid] = wcnt; }
    __syncthreads();
    if (tid == 0) {
        float s = 0.f; int c = 0;
        #pragma unroll
        for (int w = 0; w < 8; w++) { s += s_wsum[w]; c += s_wcnt[w]; }
        g_ploss[j] = s;
        g_pcnt[j]  = c;
    }
}

// ---------------------------------------------------------------------------
// Kernel 4: final reduction -> scalar loss.
// ---------------------------------------------------------------------------
__global__ void final_kernel(float* __restrict__ out) {
    const int tid = threadIdx.x;     // 512 threads
    float s = g_ploss[tid];
    float c = (float)g_pcnt[tid];
    #pragma unroll
    for (int o = 16; o; o >>= 1) {
        s += __shfl_xor_sync(0xffffffffu, s, o);
        c += __shfl_xor_sync(0xffffffffu, c, o);
    }
    __shared__ float ss[16], cc[16];
    const int lane = tid & 31, w = tid >> 5;
    if (lane == 0) { ss[w] = s; cc[w] = c; }
    __syncthreads();
    if (tid == 0) {
        float ts = 0.f, tc = 0.f;
        #pragma unroll
        for (int i = 0; i < 16; i++) { ts += ss[i]; tc += cc[i]; }
        out[0] = ts / tc;
    }
}

// ---------------------------------------------------------------------------
extern "C" void kernel_launch(void* const* d_in, const int* in_sizes, int n_in,
                              void* d_out, int out_size) {
    const float* emb = (const float*)d_in[0];
    const int* labels = (const int*)d_in[1];
    float* out = (float*)d_out;

    sq_kernel<<<BN, DN>>>(emb);
    pd_kernel<<<dim3(BN / 64, BN / 64), 256>>>(emb);
    mine_kernel<<<BN, 256>>>(labels);
    final_kernel<<<1, BN>>>(out);
}

// round 3
// speedup vs baseline: 1.3861x; 1.3861x over previous
#include <cuda_runtime.h>
#include <float.h>

#define BN 512
#define DN 256
#define NT 16            // 512 / 32 tiles per dim
#define NBLK 136         // NT*(NT+1)/2 upper-triangular tiles

// Scratch (no allocations allowed)
__device__ float g_pd[BN * BN];
__device__ float g_ploss[BN];
__device__ int   g_pcnt[BN];
__device__ unsigned int g_done;   // zero-init; reset by last CTA each call

// ---------------------------------------------------------------------------
// Kernel A: fused norms + symmetric pairwise squared distances.
// 136 CTAs (upper-tri 32x32 tiles), 128 threads (2 split-K groups x 64),
// 4x4 microtile. pd[i][j] = max(sq_i + sq_j - 2*dot, 0), diag zeroed,
// mirror block written for off-diagonal tiles.
// ---------------------------------------------------------------------------
__global__ void __launch_bounds__(128) pd_fused(const float* __restrict__ emb) {
    __shared__ float As[2][32][32];
    __shared__ float Bs[2][32][32];
    __shared__ float s_sq[2][32];

    // decode linear block -> (ti, tj), ti <= tj
    int b = blockIdx.x, ti = 0;
    while (b >= NT - ti) { b -= NT - ti; ti++; }
    const int tj = ti + b;
    const int i0 = ti * 32, j0 = tj * 32;

    const int tid = threadIdx.x;

    // ---- norm phase: 2 threads per row, 64 rows (32 A + 32 B) ----
    {
        const int which = tid >> 6;          // 0: A rows, 1: B rows
        const int r     = (tid >> 1) & 31;
        const int half  = tid & 1;
        const int row   = (which ? j0 : i0) + r;
        const float4* p = (const float4*)(emb + row * DN + half * 128);
        float s0 = 0.f, s1 = 0.f, s2 = 0.f, s3 = 0.f;
        #pragma unroll
        for (int i = 0; i < 32; i += 4) {
            float4 v;
            v = p[i + 0]; s0 = fmaf(v.x, v.x, fmaf(v.y, v.y, fmaf(v.z, v.z, fmaf(v.w, v.w, s0))));
            v = p[i + 1]; s1 = fmaf(v.x, v.x, fmaf(v.y, v.y, fmaf(v.z, v.z, fmaf(v.w, v.w, s1))));
            v = p[i + 2]; s2 = fmaf(v.x, v.x, fmaf(v.y, v.y, fmaf(v.z, v.z, fmaf(v.w, v.w, s2))));
            v = p[i + 3]; s3 = fmaf(v.x, v.x, fmaf(v.y, v.y, fmaf(v.z, v.z, fmaf(v.w, v.w, s3))));
        }
        float s = (s0 + s1) + (s2 + s3);
        s += __shfl_xor_sync(0xffffffffu, s, 1);
        if (!half) s_sq[which][r] = s;
    }

    // ---- main GEMM: split-K by 2 ----
    const int t  = tid & 63;
    const int g  = tid >> 6;         // k-group: 0 -> k[0,128), 1 -> k[128,256)
    const int lr = t >> 1;           // load row 0..31
    const int cq = (t & 1) * 4;      // float4 column quartet base
    const int ty = t >> 3;           // 0..7  -> 4 i-rows
    const int tx = t & 7;            // 0..7  -> 4 j-cols

    float acc[4][4] = {};
    const float* Arow = emb + (i0 + lr) * DN + g * 128;
    const float* Brow = emb + (j0 + lr) * DN + g * 128;

    for (int c0 = 0; c0 < 128; c0 += 32) {
        __syncthreads();
        #pragma unroll
        for (int e = 0; e < 4; e++) {
            float4 a4 = *(const float4*)(Arow + c0 + (cq + e) * 4);
            float4 b4 = *(const float4*)(Brow + c0 + (cq + e) * 4);
            const int kk = (cq + e) * 4;
            As[g][kk + 0][lr] = a4.x; As[g][kk + 1][lr] = a4.y;
            As[g][kk + 2][lr] = a4.z; As[g][kk + 3][lr] = a4.w;
            Bs[g][kk + 0][lr] = b4.x; Bs[g][kk + 1][lr] = b4.y;
            Bs[g][kk + 2][lr] = b4.z; Bs[g][kk + 3][lr] = b4.w;
        }
        __syncthreads();
        #pragma unroll
        for (int kk = 0; kk < 32; kk++) {
            float4 av = *(const float4*)&As[g][kk][ty << 2];
            float4 bv = *(const float4*)&Bs[g][kk][tx << 2];
            float ar[4] = {av.x, av.y, av.z, av.w};
            float br[4] = {bv.x, bv.y, bv.z, bv.w};
            #pragma unroll
            for (int u = 0; u < 4; u++)
                #pragma unroll
                for (int v = 0; v < 4; v++)
                    acc[u][v] = fmaf(ar[u], br[v], acc[u][v]);
        }
    }

    // ---- combine the two k-group partials via smem ----
    __syncthreads();
    if (g == 1) {
        float* dst = &As[0][0][0] + t * 16;
        #pragma unroll
        for (int u = 0; u < 4; u++)
            #pragma unroll
            for (int v = 0; v < 4; v++) dst[u * 4 + v] = acc[u][v];
    }
    __syncthreads();
    if (g == 0) {
        const float* src = &As[0][0][0] + t * 16;
        float d[4][4];
        #pragma unroll
        for (int u = 0; u < 4; u++) {
            const int gi = i0 + (ty << 2) + u;
            const float sqi = s_sq[0][(ty << 2) + u];
            #pragma unroll
            for (int v = 0; v < 4; v++) {
                const int gj = j0 + (tx << 2) + v;
                const float dot = acc[u][v] + src[u * 4 + v];
                float val = fmaxf(sqi + s_sq[1][(tx << 2) + v] - 2.f * dot, 0.f);
                if (gi == gj) val = 0.f;
                d[u][v] = val;
            }
            *(float4*)(g_pd + gi * BN + j0 + (tx << 2)) =
                make_float4(d[u][0], d[u][1], d[u][2], d[u][3]);
        }
        if (ti != tj) {
            #pragma unroll
            for (int v = 0; v < 4; v++) {
                const int gj = j0 + (tx << 2) + v;
                *(float4*)(g_pd + gj * BN + i0 + (ty << 2)) =
                    make_float4(d[0][v], d[1][v], d[2][v], d[3][v]);
            }
        }
    }
}

// ---------------------------------------------------------------------------
// Kernel B: semi-hard mining per anchor + fused final reduction (last CTA).
// ---------------------------------------------------------------------------
__global__ void __launch_bounds__(256) mine_final(const int* __restrict__ labels,
                                                  float* __restrict__ out) {
    const int j = blockIdx.x;
    const int tid = threadIdx.x;
    const int lane = tid & 31, wid = tid >> 5;

    __shared__ float row[BN];
    __shared__ unsigned char issame[BN];
    __shared__ float s_mx[8], s_mn[8], s_wsum[8];
    __shared__ int s_wcnt[8];
    __shared__ float s_neg_inside;
    __shared__ int s_last;

    const int lj = labels[j];
    float lmaxneg = -FLT_MAX;
    float lmin = FLT_MAX;
    #pragma unroll
    for (int k = tid; k < BN; k += 256) {
        float v = g_pd[j * BN + k];
        row[k] = v;
        const bool same = (labels[k] == lj);
        issame[k] = same ? 1 : 0;
        if (!same) lmaxneg = fmaxf(lmaxneg, v);
        lmin = fminf(lmin, v);
    }
    #pragma unroll
    for (int o = 16; o; o >>= 1) {
        lmaxneg = fmaxf(lmaxneg, __shfl_xor_sync(0xffffffffu, lmaxneg, o));
        lmin    = fminf(lmin,    __shfl_xor_sync(0xffffffffu, lmin,    o));
    }
    if (lane == 0) { s_mx[wid] = lmaxneg; s_mn[wid] = lmin; }
    __syncthreads();
    if (tid == 0) {
        float mx = -FLT_MAX, mn = FLT_MAX;
        #pragma unroll
        for (int w = 0; w < 8; w++) { mx = fmaxf(mx, s_mx[w]); mn = fminf(mn, s_mn[w]); }
        s_neg_inside = (mx > -FLT_MAX) ? mx : mn;
    }
    __syncthreads();

    const float ninside = s_neg_inside;
    float wsum = 0.f;
    int wcnt = 0;
    // deterministic warp-per-positive: warp w scans candidates i = w, w+8, ...
    for (int i = wid; i < BN; i += 8) {
        if (!issame[i] || i == j) continue;
        wcnt++;
        const float tpos = row[i];
        float m = FLT_MAX;
        #pragma unroll
        for (int k = lane; k < BN; k += 32) {
            const float v = row[k];
            if (!issame[k] && v > tpos) m = fminf(m, v);
        }
        #pragma unroll
        for (int o = 16; o; o >>= 1) m = fminf(m, __shfl_xor_sync(0xffffffffu, m, o));
        const float semi = (m < FLT_MAX) ? m : ninside;
        if (lane == 0) wsum += fmaxf(1.0f + tpos - semi, 0.f);
    }
    if (lane == 0) { s_wsum[wid] = wsum; s_wcnt[wid] = wcnt; }
    __syncthreads();
    if (tid == 0) {
        float s = 0.f; int c = 0;
        #pragma unroll
        for (int w = 0; w < 8; w++) { s += s_wsum[w]; c += s_wcnt[w]; }
        g_ploss[j] = s;
        g_pcnt[j]  = c;
        __threadfence();
        const unsigned int v = atomicAdd(&g_done, 1u);
        s_last = (v == (unsigned)(gridDim.x - 1)) ? 1 : 0;
    }
    __syncthreads();

    // last CTA: deterministic final reduction over fixed-order arrays
    if (s_last) {
        __threadfence();  // acquire: make all g_ploss/g_pcnt visible
        float s = g_ploss[tid] + g_ploss[tid + 256];
        float c = (float)(g_pcnt[tid] + g_pcnt[tid + 256]);
        #pragma unroll
        for (int o = 16; o; o >>= 1) {
            s += __shfl_xor_sync(0xffffffffu, s, o);
            c += __shfl_xor_sync(0xffffffffu, c, o);
        }
        __shared__ float ss[8], cc[8];
        if (lane == 0) { ss[wid] = s; cc[wid] = c; }
        __syncthreads();
        if (tid == 0) {
            float ts = 0.f, tc = 0.f;
            #pragma unroll
            for (int i = 0; i < 8; i++) { ts += ss[i]; tc += cc[i]; }
            out[0] = ts / tc;
            g_done = 0;   // reset for next graph replay
        }
    }
}

// ---------------------------------------------------------------------------
extern "C" void kernel_launch(void* const* d_in, const int* in_sizes, int n_in,
                              void* d_out, int out_size) {
    const float* emb = (const float*)d_in[0];
    const int* labels = (const int*)d_in[1];
    float* out = (float*)d_out;

    pd_fused<<<NBLK, 128>>>(emb);
    mine_final<<<BN, 256>>>(labels, out);
}

// round 4
// speedup vs baseline: 1.4009x; 1.0107x over previous
#include <cuda_runtime.h>
#include <float.h>

#define BN 512
#define DN 256
#define NT 16            // 512 / 32 tiles per dim
#define NBLK 136         // NT*(NT+1)/2 upper-triangular tiles
#define MBLK 64          // mine kernel CTAs (8 warps = 8 anchors each)

// Scratch (no allocations allowed)
__device__ float g_pd[BN * BN];
__device__ float g_ploss[BN];
__device__ int   g_pcnt[BN];
__device__ unsigned int g_done;   // zero-init; reset by last CTA each call

// ---------------------------------------------------------------------------
// Kernel A: fused norms + symmetric pairwise squared distances.
// 136 CTAs (upper-tri 32x32 tiles), 128 threads (2 split-K groups x 64),
// 4x4 microtile. pd[i][j] = max(sq_i + sq_j - 2*dot, 0), diag zeroed,
// mirror block written for off-diagonal tiles.
// ---------------------------------------------------------------------------
__global__ void __launch_bounds__(128) pd_fused(const float* __restrict__ emb) {
    __shared__ float As[2][32][32];
    __shared__ float Bs[2][32][32];
    __shared__ float s_sq[2][32];

    // decode linear block -> (ti, tj), ti <= tj
    int b = blockIdx.x, ti = 0;
    while (b >= NT - ti) { b -= NT - ti; ti++; }
    const int tj = ti + b;
    const int i0 = ti * 32, j0 = tj * 32;

    const int tid = threadIdx.x;

    // ---- norm phase: 2 threads per row, 64 rows (32 A + 32 B) ----
    {
        const int which = tid >> 6;          // 0: A rows, 1: B rows
        const int r     = (tid >> 1) & 31;
        const int half  = tid & 1;
        const int row   = (which ? j0 : i0) + r;
        const float4* p = (const float4*)(emb + row * DN + half * 128);
        float s0 = 0.f, s1 = 0.f, s2 = 0.f, s3 = 0.f;
        #pragma unroll
        for (int i = 0; i < 32; i += 4) {
            float4 v;
            v = p[i + 0]; s0 = fmaf(v.x, v.x, fmaf(v.y, v.y, fmaf(v.z, v.z, fmaf(v.w, v.w, s0))));
            v = p[i + 1]; s1 = fmaf(v.x, v.x, fmaf(v.y, v.y, fmaf(v.z, v.z, fmaf(v.w, v.w, s1))));
            v = p[i + 2]; s2 = fmaf(v.x, v.x, fmaf(v.y, v.y, fmaf(v.z, v.z, fmaf(v.w, v.w, s2))));
            v = p[i + 3]; s3 = fmaf(v.x, v.x, fmaf(v.y, v.y, fmaf(v.z, v.z, fmaf(v.w, v.w, s3))));
        }
        float s = (s0 + s1) + (s2 + s3);
        s += __shfl_xor_sync(0xffffffffu, s, 1);
        if (!half) s_sq[which][r] = s;
    }

    // ---- main GEMM: split-K by 2 ----
    const int t  = tid & 63;
    const int g  = tid >> 6;         // k-group: 0 -> k[0,128), 1 -> k[128,256)
    const int lr = t >> 1;           // load row 0..31
    const int cq = (t & 1) * 4;      // float4 column quartet base
    const int ty = t >> 3;           // 0..7  -> 4 i-rows
    const int tx = t & 7;            // 0..7  -> 4 j-cols

    float acc[4][4] = {};
    const float* Arow = emb + (i0 + lr) * DN + g * 128;
    const float* Brow = emb + (j0 + lr) * DN + g * 128;

    for (int c0 = 0; c0 < 128; c0 += 32) {
        __syncthreads();
        #pragma unroll
        for (int e = 0; e < 4; e++) {
            float4 a4 = *(const float4*)(Arow + c0 + (cq + e) * 4);
            float4 b4 = *(const float4*)(Brow + c0 + (cq + e) * 4);
            const int kk = (cq + e) * 4;
            As[g][kk + 0][lr] = a4.x; As[g][kk + 1][lr] = a4.y;
            As[g][kk + 2][lr] = a4.z; As[g][kk + 3][lr] = a4.w;
            Bs[g][kk + 0][lr] = b4.x; Bs[g][kk + 1][lr] = b4.y;
            Bs[g][kk + 2][lr] = b4.z; Bs[g][kk + 3][lr] = b4.w;
        }
        __syncthreads();
        #pragma unroll
        for (int kk = 0; kk < 32; kk++) {
            float4 av = *(const float4*)&As[g][kk][ty << 2];
            float4 bv = *(const float4*)&Bs[g][kk][tx << 2];
            float ar[4] = {av.x, av.y, av.z, av.w};
            float br[4] = {bv.x, bv.y, bv.z, bv.w};
            #pragma unroll
            for (int u = 0; u < 4; u++)
                #pragma unroll
                for (int v = 0; v < 4; v++)
                    acc[u][v] = fmaf(ar[u], br[v], acc[u][v]);
        }
    }

    // ---- combine the two k-group partials via smem ----
    __syncthreads();
    if (g == 1) {
        float* dst = &As[0][0][0] + t * 16;
        #pragma unroll
        for (int u = 0; u < 4; u++)
            #pragma unroll
            for (int v = 0; v < 4; v++) dst[u * 4 + v] = acc[u][v];
    }
    __syncthreads();
    if (g == 0) {
        const float* src = &As[0][0][0] + t * 16;
        float d[4][4];
        #pragma unroll
        for (int u = 0; u < 4; u++) {
            const int gi = i0 + (ty << 2) + u;
            const float sqi = s_sq[0][(ty << 2) + u];
            #pragma unroll
            for (int v = 0; v < 4; v++) {
                const int gj = j0 + (tx << 2) + v;
                const float dot = acc[u][v] + src[u * 4 + v];
                float val = fmaxf(sqi + s_sq[1][(tx << 2) + v] - 2.f * dot, 0.f);
                if (gi == gj) val = 0.f;
                d[u][v] = val;
            }
            *(float4*)(g_pd + gi * BN + j0 + (tx << 2)) =
                make_float4(d[u][0], d[u][1], d[u][2], d[u][3]);
        }
        if (ti != tj) {
            #pragma unroll
            for (int v = 0; v < 4; v++) {
                const int gj = j0 + (tx << 2) + v;
                *(float4*)(g_pd + gj * BN + i0 + (ty << 2)) =
                    make_float4(d[0][v], d[1][v], d[2][v], d[3][v]);
            }
        }
    }
}

// ---------------------------------------------------------------------------
// Kernel B: warp-per-anchor semi-hard mining + fused final reduction.
// 64 CTAs x 256 threads; warp w of CTA b owns anchor j = b*8 + w.
// Row lives in registers v[16] (k = c*32 + lane); nmask/pmask are 16-bit
// per-lane masks. Positives processed in pairs to overlap shfl chains.
// ---------------------------------------------------------------------------
__global__ void __launch_bounds__(256) mine_final(const int* __restrict__ labels,
                                                  float* __restrict__ out) {
    const int tid = threadIdx.x;
    const int lane = tid & 31, w = tid >> 5;
    const unsigned FULL = 0xffffffffu;

    __shared__ int   s_lab[BN];
    __shared__ float s_row[8][BN];
    __shared__ int s_last;

    for (int k = tid; k < BN; k += 256) s_lab[k] = labels[k];
    __syncthreads();

    const int j = blockIdx.x * 8 + w;          // anchor (0..511)
    const int lj = s_lab[j];
    const float* rowp = g_pd + j * BN;

    // load row into registers + smem; build negativity/positivity masks
    float v[16];
    unsigned nmask = 0, pmask = 0;
    #pragma unroll
    for (int c = 0; c < 16; c++) {
        const int k = c * 32 + lane;
        v[c] = rowp[k];
        s_row[w][k] = v[c];
        const bool same = (s_lab[k] == lj);
        if (!same) nmask |= (1u << c);
        if (same && k != j) pmask |= (1u << c);
    }

    // neg_inside: max over negatives (fallback: min over full row)
    float mx = -FLT_MAX, mn = FLT_MAX;
    #pragma unroll
    for (int c = 0; c < 16; c++) {
        if ((nmask >> c) & 1) mx = fmaxf(mx, v[c]);
        mn = fminf(mn, v[c]);
    }
    #pragma unroll
    for (int o = 16; o; o >>= 1) {
        mx = fmaxf(mx, __shfl_xor_sync(FULL, mx, o));
        mn = fminf(mn, __shfl_xor_sync(FULL, mn, o));
    }
    const float ninside = (mx > -FLT_MAX) ? mx : mn;

    // iterate positives in deterministic order, process in pairs
    float wsum = 0.f;
    int cnt = 0;
    int pend = -1;
    #pragma unroll 1
    for (int c = 0; c < 16; c++) {
        unsigned pm = __ballot_sync(FULL, (pmask >> c) & 1);
        while (pm) {
            const int b = __ffs(pm) - 1;
            pm &= pm - 1;
            const int i = c * 32 + b;
            cnt++;
            if (pend < 0) { pend = i; continue; }
            // process pair (pend, i)
            const float t1 = s_row[w][pend];
            const float t2 = s_row[w][i];
            float m1 = FLT_MAX, m2 = FLT_MAX;
            #pragma unroll
            for (int cc = 0; cc < 16; cc++) {
                if ((nmask >> cc) & 1) {
                    const float x = v[cc];
                    if (x > t1) m1 = fminf(m1, x);
                    if (x > t2) m2 = fminf(m2, x);
                }
            }
            #pragma unroll
            for (int o = 16; o; o >>= 1) {
                m1 = fminf(m1, __shfl_xor_sync(FULL, m1, o));
                m2 = fminf(m2, __shfl_xor_sync(FULL, m2, o));
            }
            const float semi1 = (m1 < FLT_MAX) ? m1 : ninside;
            const float semi2 = (m2 < FLT_MAX) ? m2 : ninside;
            wsum += fmaxf(1.0f + t1 - semi1, 0.f);
            wsum += fmaxf(1.0f + t2 - semi2, 0.f);
            pend = -1;
        }
    }
    if (pend >= 0) {
        const float t1 = s_row[w][pend];
        float m1 = FLT_MAX;
        #pragma unroll
        for (int cc = 0; cc < 16; cc++) {
            if ((nmask >> cc) & 1) {
                const float x = v[cc];
                if (x > t1) m1 = fminf(m1, x);
            }
        }
        #pragma unroll
        for (int o = 16; o; o >>= 1)
            m1 = fminf(m1, __shfl_xor_sync(FULL, m1, o));
        const float semi1 = (m1 < FLT_MAX) ? m1 : ninside;
        wsum += fmaxf(1.0f + t1 - semi1, 0.f);
    }

    if (lane == 0) {
        g_ploss[j] = wsum;
        g_pcnt[j]  = cnt;
    }
    __syncthreads();
    if (tid == 0) {
        __threadfence();
        const unsigned int vdone = atomicAdd(&g_done, 1u);
        s_last = (vdone == (unsigned)(gridDim.x - 1)) ? 1 : 0;
    }
    __syncthreads();

    // last CTA: deterministic final reduction over fixed-order arrays
    if (s_last) {
        __threadfence();  // acquire
        float s = g_ploss[tid] + g_ploss[tid + 256];
        float c = (float)(g_pcnt[tid] + g_pcnt[tid + 256]);
        #pragma unroll
        for (int o = 16; o; o >>= 1) {
            s += __shfl_xor_sync(FULL, s, o);
            c += __shfl_xor_sync(FULL, c, o);
        }
        __shared__ float ss[8], cc2[8];
        if (lane == 0) { ss[w] = s; cc2[w] = c; }
        __syncthreads();
        if (tid == 0) {
            float ts = 0.f, tc = 0.f;
            #pragma unroll
            for (int i = 0; i < 8; i++) { ts += ss[i]; tc += cc2[i]; }
            out[0] = ts / tc;
            g_done = 0;   // reset for next graph replay
        }
    }
}

// ---------------------------------------------------------------------------
extern "C" void kernel_launch(void* const* d_in, const int* in_sizes, int n_in,
                              void* d_out, int out_size) {
    const float* emb = (const float*)d_in[0];
    const int* labels = (const int*)d_in[1];
    float* out = (float*)d_out;

    pd_fused<<<NBLK, 128>>>(emb);
    mine_final<<<MBLK, 256>>>(labels, out);
}